// round 8
// baseline (speedup 1.0000x reference)
#include <cuda_runtime.h>
#include <cuda_bf16.h>
#include <cstdint>
#include <cstdio>

// ---------------------------------------------------------------------------
// EAGLE draft layer forward, sm_103a. Round 8:
//  - GEMM: 64x64 warp tiles (4 warps, 128x128 CTA), 4-stage cp.async,
//    ldmatrix + m16n8k8 TF32 mma. ~10.9 FLOP/B smem intensity.
//  - causal-aware attention (block skip + K-limit), write-limited softmax
//  - silu*up fused into up-GEMM epilogue
// ---------------------------------------------------------------------------

#define S_LEN 2048
#define H_DIM 4096
#define H2_DIM 8192
#define NHEADS 32
#define NKV 8
#define HEADD 128
#define KVDIM (NKV * HEADD)      // 1024
#define QDIM  (NHEADS * HEADD)   // 4096
#define I_DIM 11008

// flags
#define F_ROUND  1
#define F_SILU   2
#define F_CSKIP  4
#define F_PVLIM  8

// ------------------------- static scratch (fp32) ---------------------------
__device__ float g_cat[(size_t)S_LEN * H2_DIM];
__device__ float g_x1 [(size_t)S_LEN * H_DIM];
__device__ float g_h1 [(size_t)S_LEN * H_DIM];
__device__ float g_qf [(size_t)S_LEN * QDIM];
__device__ float g_kf [(size_t)S_LEN * KVDIM];
__device__ float g_vf [(size_t)S_LEN * KVDIM];
__device__ float g_vt [(size_t)KVDIM * S_LEN];
__device__ float g_sc [(size_t)NHEADS * S_LEN * S_LEN];
__device__ float g_ao [(size_t)S_LEN * QDIM];
__device__ float g_x2 [(size_t)S_LEN * H_DIM];
__device__ float g_h2 [(size_t)S_LEN * H_DIM];
__device__ float g_gf [(size_t)S_LEN * I_DIM];

// tf32-rounded weight copies
__device__ float g_wfc[(size_t)H_DIM * H2_DIM];
__device__ float g_wq [(size_t)QDIM * H_DIM];
__device__ float g_wk [(size_t)KVDIM * H_DIM];
__device__ float g_wv [(size_t)KVDIM * H_DIM];
__device__ float g_wo [(size_t)H_DIM * QDIM];
__device__ float g_wg [(size_t)I_DIM * H_DIM];
__device__ float g_wu [(size_t)I_DIM * H_DIM];
__device__ float g_wd [(size_t)H_DIM * I_DIM];

__device__ __forceinline__ float f2tf_f(float x) {
    uint32_t r;
    asm("cvt.rna.tf32.f32 %0, %1;" : "=r"(r) : "f"(x));
    return __uint_as_float(r);
}

// --------------------------- elementwise kernels ---------------------------

__global__ void cvt_tf32_kernel(const float4* __restrict__ in,
                                float4* __restrict__ out, size_t n4) {
    size_t idx = (size_t)blockIdx.x * 256 + threadIdx.x;
    if (idx < n4) {
        float4 v = in[idx];
        v.x = f2tf_f(v.x); v.y = f2tf_f(v.y); v.z = f2tf_f(v.z); v.w = f2tf_f(v.w);
        out[idx] = v;
    }
}

__global__ void concat_kernel(const float* __restrict__ emb,
                              const float* __restrict__ hid,
                              float* __restrict__ cat) {
    int idx = blockIdx.x * 256 + threadIdx.x;
    int s = idx >> 13;
    int c = idx & 8191;
    float v = (c < H_DIM) ? emb[(size_t)s * H_DIM + c]
                          : hid[(size_t)s * H_DIM + (c - H_DIM)];
    cat[idx] = f2tf_f(v);
}

__global__ __launch_bounds__(256) void rmsnorm_kernel(const float* __restrict__ x,
                                                      const float* __restrict__ w,
                                                      float* __restrict__ out) {
    int row = blockIdx.x;
    const float* xr = x + (size_t)row * H_DIM;
    float s = 0.f;
    for (int i = threadIdx.x; i < H_DIM; i += 256) { float v = xr[i]; s += v * v; }
    __shared__ float red[256];
    red[threadIdx.x] = s; __syncthreads();
    #pragma unroll
    for (int k = 128; k > 0; k >>= 1) {
        if (threadIdx.x < k) red[threadIdx.x] += red[threadIdx.x + k];
        __syncthreads();
    }
    float scale = rsqrtf(red[0] / (float)H_DIM + 1e-6f);
    for (int i = threadIdx.x; i < H_DIM; i += 256)
        out[(size_t)row * H_DIM + i] = f2tf_f(xr[i] * scale * w[i]);
}

// In-place RoPE (pos = seq index); writes tf32-rounded values.
__global__ void rope_kernel(float* __restrict__ buf, int nheads) {
    int idx = blockIdx.x * 256 + threadIdx.x;
    int total = S_LEN * nheads * 64;
    if (idx >= total) return;
    int i    = idx & 63;
    int head = (idx >> 6) % nheads;
    int s    = idx / (nheads * 64);
    float pos = (float)s;
    float inv = expf(-(float)(2 * i) * (9.210340371976184f / 128.f));
    float ang = pos * inv;
    float c = cosf(ang), sn = sinf(ang);
    size_t base = (size_t)s * (nheads * HEADD) + (size_t)head * HEADD + i;
    float x1 = buf[base], x2 = buf[base + 64];
    buf[base]      = f2tf_f(x1 * c - x2 * sn);
    buf[base + 64] = f2tf_f(x2 * c + x1 * sn);
}

__global__ void transpose_kernel(const float* __restrict__ in,
                                 float* __restrict__ out, int rows, int cols) {
    __shared__ float tile[32][33];
    int c0 = blockIdx.x * 32, r0 = blockIdx.y * 32;
    int x = threadIdx.x, y = threadIdx.y;
    #pragma unroll
    for (int j = 0; j < 32; j += 8)
        tile[y + j][x] = in[(size_t)(r0 + y + j) * cols + (c0 + x)];
    __syncthreads();
    #pragma unroll
    for (int j = 0; j < 32; j += 8)
        out[(size_t)(c0 + y + j) * rows + (r0 + x)] = f2tf_f(tile[x][y + j]);
}

// Row softmax with causal + padding mask, in place; writes only j < qEnd
// (PV GEMM never reads beyond the query's diagonal block).
__global__ __launch_bounds__(256) void softmax_kernel(float* __restrict__ sc,
                                                      const float* __restrict__ amask) {
    int i = blockIdx.x;
    int h = blockIdx.y;
    float* row = sc + ((size_t)h * S_LEN + i) * S_LEN;
    int t = threadIdx.x;
    int qEnd = ((i >> 7) + 1) << 7;
    float v[8];
    float mx = -INFINITY;
    #pragma unroll
    for (int r = 0; r < 8; r++) {
        int j = t + r * 256;
        bool ok = (j <= i) && (amask[j] > 0.5f);
        float x = ok ? row[j] : -INFINITY;
        v[r] = x;
        mx = fmaxf(mx, x);
    }
    __shared__ float red[256];
    red[t] = mx; __syncthreads();
    #pragma unroll
    for (int k = 128; k > 0; k >>= 1) {
        if (t < k) red[t] = fmaxf(red[t], red[t + k]);
        __syncthreads();
    }
    mx = red[0]; __syncthreads();
    float sum = 0.f;
    #pragma unroll
    for (int r = 0; r < 8; r++) { float e = expf(v[r] - mx); v[r] = e; sum += e; }
    red[t] = sum; __syncthreads();
    #pragma unroll
    for (int k = 128; k > 0; k >>= 1) {
        if (t < k) red[t] += red[t + k];
        __syncthreads();
    }
    float invs = 1.f / red[0];
    #pragma unroll
    for (int r = 0; r < 8; r++) {
        int j = t + r * 256;
        if (j < qEnd) row[j] = f2tf_f(v[r] * invs);
    }
}

// ----------------------------- TF32 NT GEMM --------------------------------
// C[M,N] = alpha * A[M,K] * B[N,K]^T (+bias) (+res | silu(res)*) [round].
// Pre-rounded tf32 operands. CTA 128x128, 4 warps (2x2), warp tile 64x64.
// 4-stage cp.async.cg pipeline, 20-word padded smem rows.

#define ROWW 20
#define STW (128 * ROWW)               // words per stage per matrix
#define STAGES 4
#define GEMM_SMEM (STAGES * STW * 2 * 4)   // 81920 bytes

__device__ __forceinline__ void cp16(uint32_t saddr, const float* gptr) {
    asm volatile("cp.async.cg.shared.global [%0], [%1], 16;"
                 :: "r"(saddr), "l"(__cvta_generic_to_global(gptr)));
}

__global__ __launch_bounds__(128, 2) void gemm_tf32_nt(
    const float* __restrict__ A, const float* __restrict__ B, float* __restrict__ C,
    int K, int lda, int ldb, int ldc, float alpha,
    const float* __restrict__ bias, const float* __restrict__ res, int ldres,
    long long aStride, int aDiv, long long bStride, int bDiv, long long cStride,
    int flags)
{
    int bm = blockIdx.y * 128, bn = blockIdx.x * 128;
    if ((flags & F_CSKIP) && bn >= bm + 128) return;   // fully-masked score block

    extern __shared__ __align__(16) uint32_t smem[];
    uint32_t* As = smem;
    uint32_t* Bs = smem + STAGES * STW;

    int z = blockIdx.z;
    A += (long long)(z / aDiv) * aStride;
    B += (long long)(z / bDiv) * bStride;
    C += (long long)z * cStride;

    int Keff = (flags & F_PVLIM) ? ((K < bm + 128) ? K : bm + 128) : K;

    int tid  = threadIdx.x;
    int warp = tid >> 5, lane = tid & 31;
    int wm = warp >> 1;       // 0..1
    int wn = warp & 1;        // 0..1
    int g = lane >> 2, ctg = lane & 3;

    float acc[4][8][4] = {};

    // global loaders: thread t owns row t of both tiles (4 cp16 each)
    const float* Arow = A + (size_t)(bm + tid) * lda;
    const float* Brow = B + (size_t)(bn + tid) * ldb;

    uint32_t smA = (uint32_t)__cvta_generic_to_shared(As);
    uint32_t smB = (uint32_t)__cvta_generic_to_shared(Bs);
    uint32_t stA = smA + (uint32_t)tid * (ROWW * 4);
    uint32_t stB = smB + (uint32_t)tid * (ROWW * 4);

    // ldmatrix per-lane addresses (stage 0 base)
    uint32_t aAddr = smA + ((uint32_t)(wm * 64 + (lane & 15)) * (ROWW * 4))
                   + ((uint32_t)(lane >> 4) << 4);
    uint32_t bAddr = smB + ((uint32_t)(wn * 64 + (lane & 7) + ((lane >> 4) << 3)) * (ROWW * 4))
                   + ((uint32_t)((lane >> 3) & 1) << 4);

    int nIter = Keff >> 4;

    auto issue = [&](int it) {
        if (it < nIter) {
            int k0 = it << 4;
            uint32_t so = (uint32_t)(it % STAGES) * (STW * 4);
            const float* ar = Arow + k0;
            const float* br = Brow + k0;
            #pragma unroll
            for (int c = 0; c < 4; c++) cp16(stA + so + (uint32_t)c * 16, ar + c * 4);
            #pragma unroll
            for (int c = 0; c < 4; c++) cp16(stB + so + (uint32_t)c * 16, br + c * 4);
        }
        asm volatile("cp.async.commit_group;" ::: "memory");
    };

    #pragma unroll
    for (int s = 0; s < STAGES - 1; s++) issue(s);

    for (int it = 0; it < nIter; it++) {
        asm volatile("cp.async.wait_group %0;" :: "n"(STAGES - 2) : "memory");
        __syncthreads();

        uint32_t so = (uint32_t)(it % STAGES) * (STW * 4);
        #pragma unroll
        for (int kk = 0; kk < 2; kk++) {
            uint32_t a[4][4], b[8][2];
            #pragma unroll
            for (int mt = 0; mt < 4; mt++) {
                uint32_t ad = aAddr + so + (uint32_t)(mt * 16 * ROWW * 4) + (uint32_t)(kk * 32);
                asm volatile("ldmatrix.sync.aligned.m8n8.x4.shared.b16 {%0,%1,%2,%3}, [%4];"
                             : "=r"(a[mt][0]), "=r"(a[mt][1]), "=r"(a[mt][2]), "=r"(a[mt][3])
                             : "r"(ad));
            }
            #pragma unroll
            for (int j = 0; j < 4; j++) {
                uint32_t bd = bAddr + so + (uint32_t)(j * 16 * ROWW * 4) + (uint32_t)(kk * 32);
                asm volatile("ldmatrix.sync.aligned.m8n8.x4.shared.b16 {%0,%1,%2,%3}, [%4];"
                             : "=r"(b[2*j][0]), "=r"(b[2*j][1]), "=r"(b[2*j+1][0]), "=r"(b[2*j+1][1])
                             : "r"(bd));
            }
            #pragma unroll
            for (int mt = 0; mt < 4; mt++)
                #pragma unroll
                for (int nt = 0; nt < 8; nt++)
                    asm volatile(
                        "mma.sync.aligned.m16n8k8.row.col.f32.tf32.tf32.f32 "
                        "{%0,%1,%2,%3}, {%4,%5,%6,%7}, {%8,%9}, {%0,%1,%2,%3};"
                        : "+f"(acc[mt][nt][0]), "+f"(acc[mt][nt][1]),
                          "+f"(acc[mt][nt][2]), "+f"(acc[mt][nt][3])
                        : "r"(a[mt][0]), "r"(a[mt][1]), "r"(a[mt][2]), "r"(a[mt][3]),
                          "r"(b[nt][0]), "r"(b[nt][1]));
        }

        issue(it + STAGES - 1);
    }

    // epilogue: float2 stores
    #pragma unroll
    for (int mt = 0; mt < 4; mt++) {
        int row0 = bm + wm * 64 + mt * 16 + g;
        #pragma unroll
        for (int nt = 0; nt < 8; nt++) {
            int col0 = bn + wn * 64 + nt * 8 + ctg * 2;
            #pragma unroll
            for (int half = 0; half < 2; half++) {
                int row = row0 + half * 8;
                float2 v;
                v.x = acc[mt][nt][half * 2 + 0] * alpha;
                v.y = acc[mt][nt][half * 2 + 1] * alpha;
                if (bias) { v.x += bias[col0]; v.y += bias[col0 + 1]; }
                if (res) {
                    const float2 r = *(const float2*)&res[(size_t)row * ldres + col0];
                    if (flags & F_SILU) {
                        v.x *= r.x * (1.f / (1.f + expf(-r.x)));
                        v.y *= r.y * (1.f / (1.f + expf(-r.y)));
                    } else {
                        v.x += r.x; v.y += r.y;
                    }
                }
                if (flags & F_ROUND) { v.x = f2tf_f(v.x); v.y = f2tf_f(v.y); }
                *(float2*)&C[(size_t)row * ldc + col0] = v;
            }
        }
    }
}

static inline void run_gemm(const float* A, const float* B, float* C,
                            int M, int N, int K, int lda, int ldb, int ldc,
                            float alpha, const float* bias,
                            const float* res, int ldres,
                            long long aStride, int aDiv,
                            long long bStride, int bDiv,
                            long long cStride, int batch, int flags) {
    dim3 grid(N / 128, M / 128, batch);
    gemm_tf32_nt<<<grid, 128, GEMM_SMEM>>>(A, B, C, K, lda, ldb, ldc, alpha,
                                           bias, res, ldres, aStride, aDiv,
                                           bStride, bDiv, cStride, flags);
}

// ------------------------------ orchestration ------------------------------

static inline void cvt_w(const float* in, float* out, size_t n) {
    size_t n4 = n / 4;
    cvt_tf32_kernel<<<(unsigned)((n4 + 255) / 256), 256>>>(
        (const float4*)in, (float4*)out, n4);
}

extern "C" void kernel_launch(void* const* d_in, const int* in_sizes, int n_in,
                              void* d_out, int out_size) {
    (void)in_sizes; (void)n_in; (void)out_size;
    const float* hidden  = (const float*)d_in[0];
    const float* embeds  = (const float*)d_in[1];
    const float* amask   = (const float*)d_in[2];
    const float* fc_w    = (const float*)d_in[3];
    const float* fc_b    = (const float*)d_in[4];
    const float* in_nw   = (const float*)d_in[5];
    const float* q_w     = (const float*)d_in[6];
    const float* k_w     = (const float*)d_in[7];
    const float* v_w     = (const float*)d_in[8];
    const float* o_w     = (const float*)d_in[9];
    const float* post_nw = (const float*)d_in[10];
    const float* gate_w  = (const float*)d_in[11];
    const float* up_w    = (const float*)d_in[12];
    const float* down_w  = (const float*)d_in[13];
    float* out = (float*)d_out;

    cudaFuncSetAttribute(gemm_tf32_nt,
                         cudaFuncAttributeMaxDynamicSharedMemorySize, GEMM_SMEM);

    float *cat, *x1, *h1, *qf, *kf, *vf, *vt, *sc, *ao, *x2, *h2, *gf;
    float *wfc, *wq, *wk, *wv, *wo, *wg, *wu, *wd;
    cudaGetSymbolAddress((void**)&cat, g_cat);
    cudaGetSymbolAddress((void**)&x1,  g_x1);
    cudaGetSymbolAddress((void**)&h1,  g_h1);
    cudaGetSymbolAddress((void**)&qf,  g_qf);
    cudaGetSymbolAddress((void**)&kf,  g_kf);
    cudaGetSymbolAddress((void**)&vf,  g_vf);
    cudaGetSymbolAddress((void**)&vt,  g_vt);
    cudaGetSymbolAddress((void**)&sc,  g_sc);
    cudaGetSymbolAddress((void**)&ao,  g_ao);
    cudaGetSymbolAddress((void**)&x2,  g_x2);
    cudaGetSymbolAddress((void**)&h2,  g_h2);
    cudaGetSymbolAddress((void**)&gf,  g_gf);
    cudaGetSymbolAddress((void**)&wfc, g_wfc);
    cudaGetSymbolAddress((void**)&wq,  g_wq);
    cudaGetSymbolAddress((void**)&wk,  g_wk);
    cudaGetSymbolAddress((void**)&wv,  g_wv);
    cudaGetSymbolAddress((void**)&wo,  g_wo);
    cudaGetSymbolAddress((void**)&wg,  g_wg);
    cudaGetSymbolAddress((void**)&wu,  g_wu);
    cudaGetSymbolAddress((void**)&wd,  g_wd);

    // weight rounding (once per launch)
    cvt_w(fc_w,   wfc, (size_t)H_DIM * H2_DIM);
    cvt_w(q_w,    wq,  (size_t)QDIM * H_DIM);
    cvt_w(k_w,    wk,  (size_t)KVDIM * H_DIM);
    cvt_w(v_w,    wv,  (size_t)KVDIM * H_DIM);
    cvt_w(o_w,    wo,  (size_t)H_DIM * QDIM);
    cvt_w(gate_w, wg,  (size_t)I_DIM * H_DIM);
    cvt_w(up_w,   wu,  (size_t)I_DIM * H_DIM);
    cvt_w(down_w, wd,  (size_t)H_DIM * I_DIM);

    const float scale = 0.08838834764831845f;  // 1/sqrt(128)

    // fc fusion
    concat_kernel<<<(S_LEN * H2_DIM) / 256, 256>>>(embeds, hidden, cat);
    run_gemm(cat, wfc, x1, S_LEN, H_DIM, H2_DIM, H2_DIM, H2_DIM, H_DIM,
             1.f, fc_b, nullptr, 0, 0, 1, 0, 1, 0, 1, 0);

    // attention block
    rmsnorm_kernel<<<S_LEN, 256>>>(x1, in_nw, h1);
    run_gemm(h1, wq, qf, S_LEN, QDIM,  H_DIM, H_DIM, H_DIM, QDIM,
             1.f, nullptr, nullptr, 0, 0, 1, 0, 1, 0, 1, 0);
    run_gemm(h1, wk, kf, S_LEN, KVDIM, H_DIM, H_DIM, H_DIM, KVDIM,
             1.f, nullptr, nullptr, 0, 0, 1, 0, 1, 0, 1, 0);
    run_gemm(h1, wv, vf, S_LEN, KVDIM, H_DIM, H_DIM, H_DIM, KVDIM,
             1.f, nullptr, nullptr, 0, 0, 1, 0, 1, 0, 1, 0);

    rope_kernel<<<(S_LEN * NHEADS * 64) / 256, 256>>>(qf, NHEADS);
    rope_kernel<<<(S_LEN * NKV * 64) / 256, 256>>>(kf, NKV);
    transpose_kernel<<<dim3(KVDIM / 32, S_LEN / 32), dim3(32, 8)>>>(vf, vt, S_LEN, KVDIM);

    // scores[h] = scale * Q_h K_h^T   (batched over 32 heads, causal skip)
    run_gemm(qf, kf, sc, S_LEN, S_LEN, HEADD, QDIM, KVDIM, S_LEN,
             scale, nullptr, nullptr, 0,
             (long long)HEADD, 1, (long long)HEADD, 4,
             (long long)S_LEN * S_LEN, NHEADS, F_CSKIP);
    softmax_kernel<<<dim3(S_LEN, NHEADS), 256>>>(sc, amask);
    // out[h] = P_h V_h  -> [S, NH*D]; K limited to diagonal block; round out
    run_gemm(sc, vt, ao, S_LEN, HEADD, S_LEN, S_LEN, S_LEN, QDIM,
             1.f, nullptr, nullptr, 0,
             (long long)S_LEN * S_LEN, 1, (long long)HEADD * S_LEN, 4,
             (long long)HEADD, NHEADS, F_ROUND | F_PVLIM);

    // o-proj + residual
    run_gemm(ao, wo, x2, S_LEN, H_DIM, QDIM, QDIM, QDIM, H_DIM,
             1.f, nullptr, x1, H_DIM, 0, 1, 0, 1, 0, 1, 0);

    // MLP block
    rmsnorm_kernel<<<S_LEN, 256>>>(x2, post_nw, h2);
    run_gemm(h2, wg, gf, S_LEN, I_DIM, H_DIM, H_DIM, H_DIM, I_DIM,
             1.f, nullptr, nullptr, 0, 0, 1, 0, 1, 0, 1, 0);
    // up GEMM with fused silu(gate)*up, rounded, written in place over gf
    run_gemm(h2, wu, gf, S_LEN, I_DIM, H_DIM, H_DIM, H_DIM, I_DIM,
             1.f, nullptr, gf, I_DIM, 0, 1, 0, 1, 0, 1, F_SILU | F_ROUND);
    run_gemm(gf, wd, out, S_LEN, H_DIM, I_DIM, I_DIM, I_DIM, H_DIM,
             1.f, nullptr, x2, H_DIM, 0, 1, 0, 1, 0, 1, 0);
}

// round 12
// speedup vs baseline: 1.3221x; 1.3221x over previous
#include <cuda_runtime.h>
#include <cuda_bf16.h>
#include <cstdint>
#include <cstdio>

// ---------------------------------------------------------------------------
// EAGLE draft layer forward, sm_103a. Round 9:
//  - GEMM reverted to round-7 shape (8 warps, 64x32 warp tiles, 3-stage
//    cp.async, 128 regs) + flags (causal skip, PV K-limit, silu fusion, round)
//  - write-limited softmax, silu*up fused into up GEMM
//  - weight tf32-cvt pass with 4x ILP
// ---------------------------------------------------------------------------

#define S_LEN 2048
#define H_DIM 4096
#define H2_DIM 8192
#define NHEADS 32
#define NKV 8
#define HEADD 128
#define KVDIM (NKV * HEADD)      // 1024
#define QDIM  (NHEADS * HEADD)   // 4096
#define I_DIM 11008

// flags
#define F_ROUND  1
#define F_SILU   2
#define F_CSKIP  4
#define F_PVLIM  8

// ------------------------- static scratch (fp32) ---------------------------
__device__ float g_cat[(size_t)S_LEN * H2_DIM];
__device__ float g_x1 [(size_t)S_LEN * H_DIM];
__device__ float g_h1 [(size_t)S_LEN * H_DIM];
__device__ float g_qf [(size_t)S_LEN * QDIM];
__device__ float g_kf [(size_t)S_LEN * KVDIM];
__device__ float g_vf [(size_t)S_LEN * KVDIM];
__device__ float g_vt [(size_t)KVDIM * S_LEN];
__device__ float g_sc [(size_t)NHEADS * S_LEN * S_LEN];
__device__ float g_ao [(size_t)S_LEN * QDIM];
__device__ float g_x2 [(size_t)S_LEN * H_DIM];
__device__ float g_h2 [(size_t)S_LEN * H_DIM];
__device__ float g_gf [(size_t)S_LEN * I_DIM];

// tf32-rounded weight copies
__device__ float g_wfc[(size_t)H_DIM * H2_DIM];
__device__ float g_wq [(size_t)QDIM * H_DIM];
__device__ float g_wk [(size_t)KVDIM * H_DIM];
__device__ float g_wv [(size_t)KVDIM * H_DIM];
__device__ float g_wo [(size_t)H_DIM * QDIM];
__device__ float g_wg [(size_t)I_DIM * H_DIM];
__device__ float g_wu [(size_t)I_DIM * H_DIM];
__device__ float g_wd [(size_t)H_DIM * I_DIM];

__device__ __forceinline__ float f2tf_f(float x) {
    uint32_t r;
    asm("cvt.rna.tf32.f32 %0, %1;" : "=r"(r) : "f"(x));
    return __uint_as_float(r);
}

// --------------------------- elementwise kernels ---------------------------

// 4 independent float4 per thread (MLP=4) for HBM saturation.
__global__ __launch_bounds__(256) void cvt_tf32_kernel(const float4* __restrict__ in,
                                                       float4* __restrict__ out,
                                                       size_t n4) {
    size_t base = (size_t)blockIdx.x * 1024 + threadIdx.x;
    float4 v[4];
    bool ok[4];
    #pragma unroll
    for (int i = 0; i < 4; i++) {
        size_t idx = base + (size_t)i * 256;
        ok[i] = idx < n4;
        if (ok[i]) v[i] = in[idx];
    }
    #pragma unroll
    for (int i = 0; i < 4; i++) {
        if (ok[i]) {
            v[i].x = f2tf_f(v[i].x); v[i].y = f2tf_f(v[i].y);
            v[i].z = f2tf_f(v[i].z); v[i].w = f2tf_f(v[i].w);
            out[base + (size_t)i * 256] = v[i];
        }
    }
}

__global__ void concat_kernel(const float* __restrict__ emb,
                              const float* __restrict__ hid,
                              float* __restrict__ cat) {
    int idx = blockIdx.x * 256 + threadIdx.x;
    int s = idx >> 13;
    int c = idx & 8191;
    float v = (c < H_DIM) ? emb[(size_t)s * H_DIM + c]
                          : hid[(size_t)s * H_DIM + (c - H_DIM)];
    cat[idx] = f2tf_f(v);
}

__global__ __launch_bounds__(256) void rmsnorm_kernel(const float* __restrict__ x,
                                                      const float* __restrict__ w,
                                                      float* __restrict__ out) {
    int row = blockIdx.x;
    const float* xr = x + (size_t)row * H_DIM;
    float s = 0.f;
    for (int i = threadIdx.x; i < H_DIM; i += 256) { float v = xr[i]; s += v * v; }
    __shared__ float red[256];
    red[threadIdx.x] = s; __syncthreads();
    #pragma unroll
    for (int k = 128; k > 0; k >>= 1) {
        if (threadIdx.x < k) red[threadIdx.x] += red[threadIdx.x + k];
        __syncthreads();
    }
    float scale = rsqrtf(red[0] / (float)H_DIM + 1e-6f);
    for (int i = threadIdx.x; i < H_DIM; i += 256)
        out[(size_t)row * H_DIM + i] = f2tf_f(xr[i] * scale * w[i]);
}

// In-place RoPE (pos = seq index); writes tf32-rounded values.
__global__ void rope_kernel(float* __restrict__ buf, int nheads) {
    int idx = blockIdx.x * 256 + threadIdx.x;
    int total = S_LEN * nheads * 64;
    if (idx >= total) return;
    int i    = idx & 63;
    int head = (idx >> 6) % nheads;
    int s    = idx / (nheads * 64);
    float pos = (float)s;
    float inv = expf(-(float)(2 * i) * (9.210340371976184f / 128.f));
    float ang = pos * inv;
    float c = cosf(ang), sn = sinf(ang);
    size_t base = (size_t)s * (nheads * HEADD) + (size_t)head * HEADD + i;
    float x1 = buf[base], x2 = buf[base + 64];
    buf[base]      = f2tf_f(x1 * c - x2 * sn);
    buf[base + 64] = f2tf_f(x2 * c + x1 * sn);
}

__global__ void transpose_kernel(const float* __restrict__ in,
                                 float* __restrict__ out, int rows, int cols) {
    __shared__ float tile[32][33];
    int c0 = blockIdx.x * 32, r0 = blockIdx.y * 32;
    int x = threadIdx.x, y = threadIdx.y;
    #pragma unroll
    for (int j = 0; j < 32; j += 8)
        tile[y + j][x] = in[(size_t)(r0 + y + j) * cols + (c0 + x)];
    __syncthreads();
    #pragma unroll
    for (int j = 0; j < 32; j += 8)
        out[(size_t)(c0 + y + j) * rows + (r0 + x)] = f2tf_f(tile[x][y + j]);
}

// Row softmax with causal + padding mask; writes only j < qEnd.
__global__ __launch_bounds__(256) void softmax_kernel(float* __restrict__ sc,
                                                      const float* __restrict__ amask) {
    int i = blockIdx.x;
    int h = blockIdx.y;
    float* row = sc + ((size_t)h * S_LEN + i) * S_LEN;
    int t = threadIdx.x;
    int qEnd = ((i >> 7) + 1) << 7;
    float v[8];
    float mx = -INFINITY;
    #pragma unroll
    for (int r = 0; r < 8; r++) {
        int j = t + r * 256;
        bool ok = (j <= i) && (amask[j] > 0.5f);
        float x = ok ? row[j] : -INFINITY;
        v[r] = x;
        mx = fmaxf(mx, x);
    }
    __shared__ float red[256];
    red[t] = mx; __syncthreads();
    #pragma unroll
    for (int k = 128; k > 0; k >>= 1) {
        if (t < k) red[t] = fmaxf(red[t], red[t + k]);
        __syncthreads();
    }
    mx = red[0]; __syncthreads();
    float sum = 0.f;
    #pragma unroll
    for (int r = 0; r < 8; r++) { float e = expf(v[r] - mx); v[r] = e; sum += e; }
    red[t] = sum; __syncthreads();
    #pragma unroll
    for (int k = 128; k > 0; k >>= 1) {
        if (t < k) red[t] += red[t + k];
        __syncthreads();
    }
    float invs = 1.f / red[0];
    #pragma unroll
    for (int r = 0; r < 8; r++) {
        int j = t + r * 256;
        if (j < qEnd) row[j] = f2tf_f(v[r] * invs);
    }
}

// ----------------------------- TF32 NT GEMM --------------------------------
// C[M,N] = alpha * A[M,K] * B[N,K]^T (+bias) (+res | silu(res)*) [round].
// Pre-rounded tf32 operands. CTA 128x128, 8 warps (2x4), warp tile 64x32,
// m16n8k8 TF32 mma. 3-stage cp.async.cg, 20-word padded smem rows.

#define ROWW 20
#define STW (128 * ROWW)          // words per stage per matrix
#define STAGES 3
#define GEMM_SMEM (STAGES * STW * 2 * 4)   // 61440 bytes

__device__ __forceinline__ void cp16(uint32_t saddr, const float* gptr) {
    asm volatile("cp.async.cg.shared.global [%0], [%1], 16;"
                 :: "r"(saddr), "l"(__cvta_generic_to_global(gptr)));
}

__global__ __launch_bounds__(256) void gemm_tf32_nt(
    const float* __restrict__ A, const float* __restrict__ B, float* __restrict__ C,
    int K, int lda, int ldb, int ldc, float alpha,
    const float* __restrict__ bias, const float* __restrict__ res, int ldres,
    long long aStride, int aDiv, long long bStride, int bDiv, long long cStride,
    int flags)
{
    int bm = blockIdx.y * 128, bn = blockIdx.x * 128;
    if ((flags & F_CSKIP) && bn >= bm + 128) return;   // fully-masked score block

    extern __shared__ __align__(16) uint32_t smem[];
    uint32_t* As = smem;
    uint32_t* Bs = smem + STAGES * STW;

    int z = blockIdx.z;
    A += (long long)(z / aDiv) * aStride;
    B += (long long)(z / bDiv) * bStride;
    C += (long long)z * cStride;

    int Keff = (flags & F_PVLIM) ? ((K < bm + 128) ? K : bm + 128) : K;

    int tid  = threadIdx.x;
    int warp = tid >> 5, lane = tid & 31;
    int wm = warp >> 2;       // 0..1
    int wn = warp & 3;        // 0..3
    int g = lane >> 2, ctg = lane & 3;

    float acc[4][4][4] = {};

    // global load addressing: 16B per cp.async, 4 per thread per stage
    int lrow = tid >> 2;            // 0..63
    int lcol = (tid & 3) * 4;       // 0,4,8,12
    const float* Aptr = A + (size_t)(bm + lrow) * lda + lcol;
    const float* Bptr = B + (size_t)(bn + lrow) * ldb + lcol;

    uint32_t smA = (uint32_t)__cvta_generic_to_shared(As);
    uint32_t smB = (uint32_t)__cvta_generic_to_shared(Bs);
    uint32_t stByte = (uint32_t)(lrow * ROWW + lcol) * 4;

    // ldmatrix per-lane addresses (stage 0 base)
    uint32_t aAddr = smA + ((uint32_t)(wm * 64 + (lane & 15)) * (ROWW * 4))
                   + ((uint32_t)(lane >> 4) << 4);
    uint32_t bAddr = smB + ((uint32_t)(wn * 32 + (lane & 7) + ((lane >> 4) << 3)) * (ROWW * 4))
                   + ((uint32_t)((lane >> 3) & 1) << 4);

    int nIter = Keff >> 4;

    auto issue = [&](int it) {
        if (it < nIter) {
            int k0 = it << 4;
            uint32_t slotB = (uint32_t)(it % STAGES) * (STW * 4);
            uint32_t sA = smA + slotB + stByte;
            cp16(sA, Aptr + k0);
            cp16(sA + 64 * ROWW * 4, Aptr + (size_t)64 * lda + k0);
            uint32_t sB = smB + slotB + stByte;
            cp16(sB, Bptr + k0);
            cp16(sB + 64 * ROWW * 4, Bptr + (size_t)64 * ldb + k0);
        }
        asm volatile("cp.async.commit_group;" ::: "memory");
    };

    #pragma unroll
    for (int s = 0; s < STAGES - 1; s++) issue(s);

    for (int it = 0; it < nIter; it++) {
        asm volatile("cp.async.wait_group %0;" :: "n"(STAGES - 2) : "memory");
        __syncthreads();

        uint32_t slotB = (uint32_t)(it % STAGES) * (STW * 4);
        #pragma unroll
        for (int kk = 0; kk < 2; kk++) {
            uint32_t a[4][4], b[4][2];
            #pragma unroll
            for (int mt = 0; mt < 4; mt++) {
                uint32_t ad = aAddr + slotB + (uint32_t)(mt * 16 * ROWW * 4) + (uint32_t)(kk * 32);
                asm volatile("ldmatrix.sync.aligned.m8n8.x4.shared.b16 {%0,%1,%2,%3}, [%4];"
                             : "=r"(a[mt][0]), "=r"(a[mt][1]), "=r"(a[mt][2]), "=r"(a[mt][3])
                             : "r"(ad));
            }
            #pragma unroll
            for (int j = 0; j < 2; j++) {
                uint32_t bd = bAddr + slotB + (uint32_t)(j * 16 * ROWW * 4) + (uint32_t)(kk * 32);
                asm volatile("ldmatrix.sync.aligned.m8n8.x4.shared.b16 {%0,%1,%2,%3}, [%4];"
                             : "=r"(b[2*j][0]), "=r"(b[2*j][1]), "=r"(b[2*j+1][0]), "=r"(b[2*j+1][1])
                             : "r"(bd));
            }
            #pragma unroll
            for (int mt = 0; mt < 4; mt++)
                #pragma unroll
                for (int nt = 0; nt < 4; nt++)
                    asm volatile(
                        "mma.sync.aligned.m16n8k8.row.col.f32.tf32.tf32.f32 "
                        "{%0,%1,%2,%3}, {%4,%5,%6,%7}, {%8,%9}, {%0,%1,%2,%3};"
                        : "+f"(acc[mt][nt][0]), "+f"(acc[mt][nt][1]),
                          "+f"(acc[mt][nt][2]), "+f"(acc[mt][nt][3])
                        : "r"(a[mt][0]), "r"(a[mt][1]), "r"(a[mt][2]), "r"(a[mt][3]),
                          "r"(b[nt][0]), "r"(b[nt][1]));
        }

        issue(it + STAGES - 1);
    }

    // epilogue: float2 stores
    #pragma unroll
    for (int mt = 0; mt < 4; mt++) {
        int row0 = bm + wm * 64 + mt * 16 + g;
        #pragma unroll
        for (int nt = 0; nt < 4; nt++) {
            int col0 = bn + wn * 32 + nt * 8 + ctg * 2;
            #pragma unroll
            for (int half = 0; half < 2; half++) {
                int row = row0 + half * 8;
                float2 v;
                v.x = acc[mt][nt][half * 2 + 0] * alpha;
                v.y = acc[mt][nt][half * 2 + 1] * alpha;
                if (bias) { v.x += bias[col0]; v.y += bias[col0 + 1]; }
                if (res) {
                    const float2 r = *(const float2*)&res[(size_t)row * ldres + col0];
                    if (flags & F_SILU) {
                        v.x *= r.x * (1.f / (1.f + expf(-r.x)));
                        v.y *= r.y * (1.f / (1.f + expf(-r.y)));
                    } else {
                        v.x += r.x; v.y += r.y;
                    }
                }
                if (flags & F_ROUND) { v.x = f2tf_f(v.x); v.y = f2tf_f(v.y); }
                *(float2*)&C[(size_t)row * ldc + col0] = v;
            }
        }
    }
}

static inline void run_gemm(const float* A, const float* B, float* C,
                            int M, int N, int K, int lda, int ldb, int ldc,
                            float alpha, const float* bias,
                            const float* res, int ldres,
                            long long aStride, int aDiv,
                            long long bStride, int bDiv,
                            long long cStride, int batch, int flags) {
    dim3 grid(N / 128, M / 128, batch);
    gemm_tf32_nt<<<grid, 256, GEMM_SMEM>>>(A, B, C, K, lda, ldb, ldc, alpha,
                                           bias, res, ldres, aStride, aDiv,
                                           bStride, bDiv, cStride, flags);
}

// ------------------------------ orchestration ------------------------------

static inline void cvt_w(const float* in, float* out, size_t n) {
    size_t n4 = n / 4;
    cvt_tf32_kernel<<<(unsigned)((n4 + 1023) / 1024), 256>>>(
        (const float4*)in, (float4*)out, n4);
}

extern "C" void kernel_launch(void* const* d_in, const int* in_sizes, int n_in,
                              void* d_out, int out_size) {
    (void)in_sizes; (void)n_in; (void)out_size;
    const float* hidden  = (const float*)d_in[0];
    const float* embeds  = (const float*)d_in[1];
    const float* amask   = (const float*)d_in[2];
    const float* fc_w    = (const float*)d_in[3];
    const float* fc_b    = (const float*)d_in[4];
    const float* in_nw   = (const float*)d_in[5];
    const float* q_w     = (const float*)d_in[6];
    const float* k_w     = (const float*)d_in[7];
    const float* v_w     = (const float*)d_in[8];
    const float* o_w     = (const float*)d_in[9];
    const float* post_nw = (const float*)d_in[10];
    const float* gate_w  = (const float*)d_in[11];
    const float* up_w    = (const float*)d_in[12];
    const float* down_w  = (const float*)d_in[13];
    float* out = (float*)d_out;

    cudaFuncSetAttribute(gemm_tf32_nt,
                         cudaFuncAttributeMaxDynamicSharedMemorySize, GEMM_SMEM);

    float *cat, *x1, *h1, *qf, *kf, *vf, *vt, *sc, *ao, *x2, *h2, *gf;
    float *wfc, *wq, *wk, *wv, *wo, *wg, *wu, *wd;
    cudaGetSymbolAddress((void**)&cat, g_cat);
    cudaGetSymbolAddress((void**)&x1,  g_x1);
    cudaGetSymbolAddress((void**)&h1,  g_h1);
    cudaGetSymbolAddress((void**)&qf,  g_qf);
    cudaGetSymbolAddress((void**)&kf,  g_kf);
    cudaGetSymbolAddress((void**)&vf,  g_vf);
    cudaGetSymbolAddress((void**)&vt,  g_vt);
    cudaGetSymbolAddress((void**)&sc,  g_sc);
    cudaGetSymbolAddress((void**)&ao,  g_ao);
    cudaGetSymbolAddress((void**)&x2,  g_x2);
    cudaGetSymbolAddress((void**)&h2,  g_h2);
    cudaGetSymbolAddress((void**)&gf,  g_gf);
    cudaGetSymbolAddress((void**)&wfc, g_wfc);
    cudaGetSymbolAddress((void**)&wq,  g_wq);
    cudaGetSymbolAddress((void**)&wk,  g_wk);
    cudaGetSymbolAddress((void**)&wv,  g_wv);
    cudaGetSymbolAddress((void**)&wo,  g_wo);
    cudaGetSymbolAddress((void**)&wg,  g_wg);
    cudaGetSymbolAddress((void**)&wu,  g_wu);
    cudaGetSymbolAddress((void**)&wd,  g_wd);

    // weight rounding (once per launch)
    cvt_w(fc_w,   wfc, (size_t)H_DIM * H2_DIM);
    cvt_w(q_w,    wq,  (size_t)QDIM * H_DIM);
    cvt_w(k_w,    wk,  (size_t)KVDIM * H_DIM);
    cvt_w(v_w,    wv,  (size_t)KVDIM * H_DIM);
    cvt_w(o_w,    wo,  (size_t)H_DIM * QDIM);
    cvt_w(gate_w, wg,  (size_t)I_DIM * H_DIM);
    cvt_w(up_w,   wu,  (size_t)I_DIM * H_DIM);
    cvt_w(down_w, wd,  (size_t)H_DIM * I_DIM);

    const float scale = 0.08838834764831845f;  // 1/sqrt(128)

    // fc fusion
    concat_kernel<<<(S_LEN * H2_DIM) / 256, 256>>>(embeds, hidden, cat);
    run_gemm(cat, wfc, x1, S_LEN, H_DIM, H2_DIM, H2_DIM, H2_DIM, H_DIM,
             1.f, fc_b, nullptr, 0, 0, 1, 0, 1, 0, 1, 0);

    // attention block
    rmsnorm_kernel<<<S_LEN, 256>>>(x1, in_nw, h1);
    run_gemm(h1, wq, qf, S_LEN, QDIM,  H_DIM, H_DIM, H_DIM, QDIM,
             1.f, nullptr, nullptr, 0, 0, 1, 0, 1, 0, 1, 0);
    run_gemm(h1, wk, kf, S_LEN, KVDIM, H_DIM, H_DIM, H_DIM, KVDIM,
             1.f, nullptr, nullptr, 0, 0, 1, 0, 1, 0, 1, 0);
    run_gemm(h1, wv, vf, S_LEN, KVDIM, H_DIM, H_DIM, H_DIM, KVDIM,
             1.f, nullptr, nullptr, 0, 0, 1, 0, 1, 0, 1, 0);

    rope_kernel<<<(S_LEN * NHEADS * 64) / 256, 256>>>(qf, NHEADS);
    rope_kernel<<<(S_LEN * NKV * 64) / 256, 256>>>(kf, NKV);
    transpose_kernel<<<dim3(KVDIM / 32, S_LEN / 32), dim3(32, 8)>>>(vf, vt, S_LEN, KVDIM);

    // scores[h] = scale * Q_h K_h^T   (batched over 32 heads, causal skip)
    run_gemm(qf, kf, sc, S_LEN, S_LEN, HEADD, QDIM, KVDIM, S_LEN,
             scale, nullptr, nullptr, 0,
             (long long)HEADD, 1, (long long)HEADD, 4,
             (long long)S_LEN * S_LEN, NHEADS, F_CSKIP);
    softmax_kernel<<<dim3(S_LEN, NHEADS), 256>>>(sc, amask);
    // out[h] = P_h V_h  -> [S, NH*D]; K limited to diagonal block; round out
    run_gemm(sc, vt, ao, S_LEN, HEADD, S_LEN, S_LEN, S_LEN, QDIM,
             1.f, nullptr, nullptr, 0,
             (long long)S_LEN * S_LEN, 1, (long long)HEADD * S_LEN, 4,
             (long long)HEADD, NHEADS, F_ROUND | F_PVLIM);

    // o-proj + residual
    run_gemm(ao, wo, x2, S_LEN, H_DIM, QDIM, QDIM, QDIM, H_DIM,
             1.f, nullptr, x1, H_DIM, 0, 1, 0, 1, 0, 1, 0);

    // MLP block
    rmsnorm_kernel<<<S_LEN, 256>>>(x2, post_nw, h2);
    run_gemm(h2, wg, gf, S_LEN, I_DIM, H_DIM, H_DIM, H_DIM, I_DIM,
             1.f, nullptr, nullptr, 0, 0, 1, 0, 1, 0, 1, 0);
    // up GEMM with fused silu(gate)*up, rounded, written in place over gf
    run_gemm(h2, wu, gf, S_LEN, I_DIM, H_DIM, H_DIM, H_DIM, I_DIM,
             1.f, nullptr, gf, I_DIM, 0, 1, 0, 1, 0, 1, F_SILU | F_ROUND);
    run_gemm(gf, wd, out, S_LEN, H_DIM, I_DIM, I_DIM, I_DIM, H_DIM,
             1.f, nullptr, x2, H_DIM, 0, 1, 0, 1, 0, 1, 0);
}

// round 13
// speedup vs baseline: 2.6367x; 1.9943x over previous
#include <cuda_runtime.h>
#include <cuda_fp16.h>
#include <cstdint>
#include <cstdio>

// ---------------------------------------------------------------------------
// EAGLE draft layer forward, sm_103a. Round 13: FP16 GEMM datapath
// (m16n8k16 HMMA, fp32 accumulate). Same 10-bit mantissa as tf32 ->
// same rounding error; 2x FLOP/smem-byte, 2x less HBM traffic.
// fp32 kept for: residual streams, scores+softmax, final output.
// ---------------------------------------------------------------------------

#define S_LEN 2048
#define H_DIM 4096
#define H2_DIM 8192
#define NHEADS 32
#define NKV 8
#define HEADD 128
#define KVDIM (NKV * HEADD)      // 1024
#define QDIM  (NHEADS * HEADD)   // 4096
#define I_DIM 11008

// flags
#define F_SILU     1
#define F_CSKIP    2
#define F_PVLIM    4
#define F_OUTHALF  8
#define F_RESHALF 16

// ------------------------- static scratch ----------------------------------
__device__ __half g_cat[(size_t)S_LEN * H2_DIM];
__device__ float  g_x1 [(size_t)S_LEN * H_DIM];
__device__ __half g_h1 [(size_t)S_LEN * H_DIM];
__device__ __half g_qf [(size_t)S_LEN * QDIM];
__device__ __half g_kf [(size_t)S_LEN * KVDIM];
__device__ __half g_vf [(size_t)S_LEN * KVDIM];
__device__ __half g_vt [(size_t)KVDIM * S_LEN];
__device__ float  g_sc [(size_t)NHEADS * S_LEN * S_LEN];   // fp32 scores
__device__ __half g_pr [(size_t)NHEADS * S_LEN * S_LEN];   // fp16 probs
__device__ __half g_ao [(size_t)S_LEN * QDIM];
__device__ float  g_x2 [(size_t)S_LEN * H_DIM];
__device__ __half g_h2 [(size_t)S_LEN * H_DIM];
__device__ __half g_gf [(size_t)S_LEN * I_DIM];

// fp16 weight copies
__device__ __half g_wfc[(size_t)H_DIM * H2_DIM];
__device__ __half g_wq [(size_t)QDIM * H_DIM];
__device__ __half g_wk [(size_t)KVDIM * H_DIM];
__device__ __half g_wv [(size_t)KVDIM * H_DIM];
__device__ __half g_wo [(size_t)H_DIM * QDIM];
__device__ __half g_wg [(size_t)I_DIM * H_DIM];
__device__ __half g_wu [(size_t)I_DIM * H_DIM];
__device__ __half g_wd [(size_t)H_DIM * I_DIM];

// --------------------------- elementwise kernels ---------------------------

// fp32 -> fp16 weight conversion, 4 float4 per thread.
__global__ __launch_bounds__(256) void cvt_f16_kernel(const float4* __restrict__ in,
                                                      uint2* __restrict__ out,
                                                      size_t n4) {
    size_t base = (size_t)blockIdx.x * 1024 + threadIdx.x;
    float4 v[4];
    bool ok[4];
    #pragma unroll
    for (int i = 0; i < 4; i++) {
        size_t idx = base + (size_t)i * 256;
        ok[i] = idx < n4;
        if (ok[i]) v[i] = in[idx];
    }
    #pragma unroll
    for (int i = 0; i < 4; i++) {
        if (ok[i]) {
            __half2 lo = __floats2half2_rn(v[i].x, v[i].y);
            __half2 hi = __floats2half2_rn(v[i].z, v[i].w);
            uint2 u;
            u.x = *(uint32_t*)&lo;
            u.y = *(uint32_t*)&hi;
            out[base + (size_t)i * 256] = u;
        }
    }
}

__global__ void concat_kernel(const float* __restrict__ emb,
                              const float* __restrict__ hid,
                              __half* __restrict__ cat) {
    int idx = blockIdx.x * 256 + threadIdx.x;
    int s = idx >> 13;
    int c = idx & 8191;
    float v = (c < H_DIM) ? emb[(size_t)s * H_DIM + c]
                          : hid[(size_t)s * H_DIM + (c - H_DIM)];
    cat[idx] = __float2half_rn(v);
}

__global__ __launch_bounds__(256) void rmsnorm_kernel(const float* __restrict__ x,
                                                      const float* __restrict__ w,
                                                      __half* __restrict__ out) {
    int row = blockIdx.x;
    const float* xr = x + (size_t)row * H_DIM;
    float s = 0.f;
    for (int i = threadIdx.x; i < H_DIM; i += 256) { float v = xr[i]; s += v * v; }
    __shared__ float red[256];
    red[threadIdx.x] = s; __syncthreads();
    #pragma unroll
    for (int k = 128; k > 0; k >>= 1) {
        if (threadIdx.x < k) red[threadIdx.x] += red[threadIdx.x + k];
        __syncthreads();
    }
    float scale = rsqrtf(red[0] / (float)H_DIM + 1e-6f);
    for (int i = threadIdx.x; i < H_DIM; i += 256)
        out[(size_t)row * H_DIM + i] = __float2half_rn(xr[i] * scale * w[i]);
}

// In-place RoPE on fp16 buffer (pos = seq index), fp32 math.
__global__ void rope_kernel(__half* __restrict__ buf, int nheads) {
    int idx = blockIdx.x * 256 + threadIdx.x;
    int total = S_LEN * nheads * 64;
    if (idx >= total) return;
    int i    = idx & 63;
    int head = (idx >> 6) % nheads;
    int s    = idx / (nheads * 64);
    float pos = (float)s;
    float inv = expf(-(float)(2 * i) * (9.210340371976184f / 128.f));
    float ang = pos * inv;
    float c = cosf(ang), sn = sinf(ang);
    size_t base = (size_t)s * (nheads * HEADD) + (size_t)head * HEADD + i;
    float x1 = __half2float(buf[base]), x2 = __half2float(buf[base + 64]);
    buf[base]      = __float2half_rn(x1 * c - x2 * sn);
    buf[base + 64] = __float2half_rn(x2 * c + x1 * sn);
}

__global__ void transpose_kernel(const __half* __restrict__ in,
                                 __half* __restrict__ out, int rows, int cols) {
    __shared__ __half tile[32][34];
    int c0 = blockIdx.x * 32, r0 = blockIdx.y * 32;
    int x = threadIdx.x, y = threadIdx.y;
    #pragma unroll
    for (int j = 0; j < 32; j += 8)
        tile[y + j][x] = in[(size_t)(r0 + y + j) * cols + (c0 + x)];
    __syncthreads();
    #pragma unroll
    for (int j = 0; j < 32; j += 8)
        out[(size_t)(c0 + y + j) * rows + (r0 + x)] = tile[x][y + j];
}

// Row softmax (fp32 scores in) writing fp16 probs, only j < qEnd.
__global__ __launch_bounds__(256) void softmax_kernel(const float* __restrict__ sc,
                                                      __half* __restrict__ pr,
                                                      const float* __restrict__ amask) {
    int i = blockIdx.x;
    int h = blockIdx.y;
    const float* row = sc + ((size_t)h * S_LEN + i) * S_LEN;
    __half* prow = pr + ((size_t)h * S_LEN + i) * S_LEN;
    int t = threadIdx.x;
    int qEnd = ((i >> 7) + 1) << 7;
    float v[8];
    float mx = -INFINITY;
    #pragma unroll
    for (int r = 0; r < 8; r++) {
        int j = t + r * 256;
        bool ok = (j <= i) && (amask[j] > 0.5f);
        float x = ok ? row[j] : -INFINITY;
        v[r] = x;
        mx = fmaxf(mx, x);
    }
    __shared__ float red[256];
    red[t] = mx; __syncthreads();
    #pragma unroll
    for (int k = 128; k > 0; k >>= 1) {
        if (t < k) red[t] = fmaxf(red[t], red[t + k]);
        __syncthreads();
    }
    mx = red[0]; __syncthreads();
    float sum = 0.f;
    #pragma unroll
    for (int r = 0; r < 8; r++) { float e = expf(v[r] - mx); v[r] = e; sum += e; }
    red[t] = sum; __syncthreads();
    #pragma unroll
    for (int k = 128; k > 0; k >>= 1) {
        if (t < k) red[t] += red[t + k];
        __syncthreads();
    }
    float invs = 1.f / red[0];
    #pragma unroll
    for (int r = 0; r < 8; r++) {
        int j = t + r * 256;
        if (j < qEnd) prow[j] = __float2half_rn(v[r] * invs);
    }
}

// ----------------------------- FP16 NT GEMM --------------------------------
// C[M,N] = alpha * A[M,K] * B[N,K]^T (+bias) (+res | silu(res)*).
// fp16 operands, fp32 accumulate. CTA 128x128, 8 warps (2x4), warp 64x32,
// m16n8k16 HMMA. BK=32 (64B rows, padded to 80B). 4-stage cp.async.cg.

#define ROWH 40                        // smem row width in halfs (80 B)
#define STH (128 * ROWH)               // halfs per stage per matrix
#define STAGES 4
#define GEMM_SMEM (STAGES * STH * 2 * 2)   // 81920 bytes

__device__ __forceinline__ void cp16(uint32_t saddr, const __half* gptr) {
    asm volatile("cp.async.cg.shared.global [%0], [%1], 16;"
                 :: "r"(saddr), "l"(__cvta_generic_to_global(gptr)));
}

__global__ __launch_bounds__(256) void gemm_f16_nt(
    const __half* __restrict__ A, const __half* __restrict__ B, void* __restrict__ Cv,
    int K, int lda, int ldb, int ldc, float alpha,
    const float* __restrict__ bias, const void* __restrict__ res, int ldres,
    long long aStride, int aDiv, long long bStride, int bDiv, long long cStride,
    int flags)
{
    int bm = blockIdx.y * 128, bn = blockIdx.x * 128;
    if ((flags & F_CSKIP) && bn >= bm + 128) return;   // fully-masked score block

    extern __shared__ __align__(16) __half smem[];
    __half* As = smem;
    __half* Bs = smem + STAGES * STH;

    int z = blockIdx.z;
    A += (long long)(z / aDiv) * aStride;
    B += (long long)(z / bDiv) * bStride;

    int Keff = (flags & F_PVLIM) ? ((K < bm + 128) ? K : bm + 128) : K;

    int tid  = threadIdx.x;
    int warp = tid >> 5, lane = tid & 31;
    int wm = warp >> 2;       // 0..1
    int wn = warp & 3;        // 0..3
    int g = lane >> 2, ctg = lane & 3;

    float acc[4][4][4] = {};

    // global loads: 16B (8 halfs) per cp.async; 2 per matrix per stage
    int lrow = tid >> 2;            // 0..63
    int lcol = (tid & 3) * 8;       // 0,8,16,24 halfs
    const __half* Aptr = A + (size_t)(bm + lrow) * lda + lcol;
    const __half* Bptr = B + (size_t)(bn + lrow) * ldb + lcol;

    uint32_t smA = (uint32_t)__cvta_generic_to_shared(As);
    uint32_t smB = (uint32_t)__cvta_generic_to_shared(Bs);
    uint32_t stByte = (uint32_t)(lrow * ROWH + lcol) * 2;

    // ldmatrix per-lane addresses (stage 0 base), 16B units
    uint32_t aAddr = smA + ((uint32_t)(wm * 64 + (lane & 15)) * (ROWH * 2))
                   + ((uint32_t)(lane >> 4) << 4);
    uint32_t bAddr = smB + ((uint32_t)(wn * 32 + (lane & 7) + ((lane >> 4) << 3)) * (ROWH * 2))
                   + ((uint32_t)((lane >> 3) & 1) << 4);

    int nIter = Keff >> 5;     // BK = 32

    auto issue = [&](int it) {
        if (it < nIter) {
            int k0 = it << 5;
            uint32_t slotB = (uint32_t)(it % STAGES) * (STH * 2);
            uint32_t sA = smA + slotB + stByte;
            cp16(sA, Aptr + k0);
            cp16(sA + 64 * ROWH * 2, Aptr + (size_t)64 * lda + k0);
            uint32_t sB = smB + slotB + stByte;
            cp16(sB, Bptr + k0);
            cp16(sB + 64 * ROWH * 2, Bptr + (size_t)64 * ldb + k0);
        }
        asm volatile("cp.async.commit_group;" ::: "memory");
    };

    #pragma unroll
    for (int s = 0; s < STAGES - 1; s++) issue(s);

    for (int it = 0; it < nIter; it++) {
        asm volatile("cp.async.wait_group %0;" :: "n"(STAGES - 2) : "memory");
        __syncthreads();

        uint32_t slotB = (uint32_t)(it % STAGES) * (STH * 2);
        #pragma unroll
        for (int kk = 0; kk < 2; kk++) {       // two k16 halves of BK=32
            uint32_t a[4][4], b[4][2];
            #pragma unroll
            for (int mt = 0; mt < 4; mt++) {
                uint32_t ad = aAddr + slotB + (uint32_t)(mt * 16 * ROWH * 2) + (uint32_t)(kk * 32);
                asm volatile("ldmatrix.sync.aligned.m8n8.x4.shared.b16 {%0,%1,%2,%3}, [%4];"
                             : "=r"(a[mt][0]), "=r"(a[mt][1]), "=r"(a[mt][2]), "=r"(a[mt][3])
                             : "r"(ad));
            }
            #pragma unroll
            for (int j = 0; j < 2; j++) {
                uint32_t bd = bAddr + slotB + (uint32_t)(j * 16 * ROWH * 2) + (uint32_t)(kk * 32);
                asm volatile("ldmatrix.sync.aligned.m8n8.x4.shared.b16 {%0,%1,%2,%3}, [%4];"
                             : "=r"(b[2*j][0]), "=r"(b[2*j][1]), "=r"(b[2*j+1][0]), "=r"(b[2*j+1][1])
                             : "r"(bd));
            }
            #pragma unroll
            for (int mt = 0; mt < 4; mt++)
                #pragma unroll
                for (int nt = 0; nt < 4; nt++)
                    asm volatile(
                        "mma.sync.aligned.m16n8k16.row.col.f32.f16.f16.f32 "
                        "{%0,%1,%2,%3}, {%4,%5,%6,%7}, {%8,%9}, {%0,%1,%2,%3};"
                        : "+f"(acc[mt][nt][0]), "+f"(acc[mt][nt][1]),
                          "+f"(acc[mt][nt][2]), "+f"(acc[mt][nt][3])
                        : "r"(a[mt][0]), "r"(a[mt][1]), "r"(a[mt][2]), "r"(a[mt][3]),
                          "r"(b[nt][0]), "r"(b[nt][1]));
        }

        issue(it + STAGES - 1);
    }

    // epilogue
    #pragma unroll
    for (int mt = 0; mt < 4; mt++) {
        int row0 = bm + wm * 64 + mt * 16 + g;
        #pragma unroll
        for (int nt = 0; nt < 4; nt++) {
            int col0 = bn + wn * 32 + nt * 8 + ctg * 2;
            #pragma unroll
            for (int half = 0; half < 2; half++) {
                int row = row0 + half * 8;
                float vx = acc[mt][nt][half * 2 + 0] * alpha;
                float vy = acc[mt][nt][half * 2 + 1] * alpha;
                if (bias) { vx += bias[col0]; vy += bias[col0 + 1]; }
                if (res) {
                    float rx, ry;
                    if (flags & F_RESHALF) {
                        const __half2 rh = *(const __half2*)
                            ((const __half*)res + (size_t)row * ldres + col0);
                        float2 rf = __half22float2(rh);
                        rx = rf.x; ry = rf.y;
                    } else {
                        const float2 rf = *(const float2*)
                            ((const float*)res + (size_t)row * ldres + col0);
                        rx = rf.x; ry = rf.y;
                    }
                    if (flags & F_SILU) {
                        vx *= rx * (1.f / (1.f + expf(-rx)));
                        vy *= ry * (1.f / (1.f + expf(-ry)));
                    } else {
                        vx += rx; vy += ry;
                    }
                }
                if (flags & F_OUTHALF) {
                    __half* C = (__half*)Cv + (long long)z * cStride;
                    *(__half2*)&C[(size_t)row * ldc + col0] = __floats2half2_rn(vx, vy);
                } else {
                    float* C = (float*)Cv + (long long)z * cStride;
                    float2 v2; v2.x = vx; v2.y = vy;
                    *(float2*)&C[(size_t)row * ldc + col0] = v2;
                }
            }
        }
    }
}

static inline void run_gemm(const __half* A, const __half* B, void* C,
                            int M, int N, int K, int lda, int ldb, int ldc,
                            float alpha, const float* bias,
                            const void* res, int ldres,
                            long long aStride, int aDiv,
                            long long bStride, int bDiv,
                            long long cStride, int batch, int flags) {
    dim3 grid(N / 128, M / 128, batch);
    gemm_f16_nt<<<grid, 256, GEMM_SMEM>>>(A, B, C, K, lda, ldb, ldc, alpha,
                                          bias, res, ldres, aStride, aDiv,
                                          bStride, bDiv, cStride, flags);
}

// ------------------------------ orchestration ------------------------------

static inline void cvt_w(const float* in, __half* out, size_t n) {
    size_t n4 = n / 4;
    cvt_f16_kernel<<<(unsigned)((n4 + 1023) / 1024), 256>>>(
        (const float4*)in, (uint2*)out, n4);
}

extern "C" void kernel_launch(void* const* d_in, const int* in_sizes, int n_in,
                              void* d_out, int out_size) {
    (void)in_sizes; (void)n_in; (void)out_size;
    const float* hidden  = (const float*)d_in[0];
    const float* embeds  = (const float*)d_in[1];
    const float* amask   = (const float*)d_in[2];
    const float* fc_w    = (const float*)d_in[3];
    const float* fc_b    = (const float*)d_in[4];
    const float* in_nw   = (const float*)d_in[5];
    const float* q_w     = (const float*)d_in[6];
    const float* k_w     = (const float*)d_in[7];
    const float* v_w     = (const float*)d_in[8];
    const float* o_w     = (const float*)d_in[9];
    const float* post_nw = (const float*)d_in[10];
    const float* gate_w  = (const float*)d_in[11];
    const float* up_w    = (const float*)d_in[12];
    const float* down_w  = (const float*)d_in[13];
    float* out = (float*)d_out;

    cudaFuncSetAttribute(gemm_f16_nt,
                         cudaFuncAttributeMaxDynamicSharedMemorySize, GEMM_SMEM);

    __half *cat, *h1, *qf, *kf, *vf, *vt, *pr, *ao, *h2, *gf;
    float *x1, *sc, *x2;
    __half *wfc, *wq, *wk, *wv, *wo, *wg, *wu, *wd;
    cudaGetSymbolAddress((void**)&cat, g_cat);
    cudaGetSymbolAddress((void**)&x1,  g_x1);
    cudaGetSymbolAddress((void**)&h1,  g_h1);
    cudaGetSymbolAddress((void**)&qf,  g_qf);
    cudaGetSymbolAddress((void**)&kf,  g_kf);
    cudaGetSymbolAddress((void**)&vf,  g_vf);
    cudaGetSymbolAddress((void**)&vt,  g_vt);
    cudaGetSymbolAddress((void**)&sc,  g_sc);
    cudaGetSymbolAddress((void**)&pr,  g_pr);
    cudaGetSymbolAddress((void**)&ao,  g_ao);
    cudaGetSymbolAddress((void**)&x2,  g_x2);
    cudaGetSymbolAddress((void**)&h2,  g_h2);
    cudaGetSymbolAddress((void**)&gf,  g_gf);
    cudaGetSymbolAddress((void**)&wfc, g_wfc);
    cudaGetSymbolAddress((void**)&wq,  g_wq);
    cudaGetSymbolAddress((void**)&wk,  g_wk);
    cudaGetSymbolAddress((void**)&wv,  g_wv);
    cudaGetSymbolAddress((void**)&wo,  g_wo);
    cudaGetSymbolAddress((void**)&wg,  g_wg);
    cudaGetSymbolAddress((void**)&wu,  g_wu);
    cudaGetSymbolAddress((void**)&wd,  g_wd);

    // weight conversion (once per launch)
    cvt_w(fc_w,   wfc, (size_t)H_DIM * H2_DIM);
    cvt_w(q_w,    wq,  (size_t)QDIM * H_DIM);
    cvt_w(k_w,    wk,  (size_t)KVDIM * H_DIM);
    cvt_w(v_w,    wv,  (size_t)KVDIM * H_DIM);
    cvt_w(o_w,    wo,  (size_t)H_DIM * QDIM);
    cvt_w(gate_w, wg,  (size_t)I_DIM * H_DIM);
    cvt_w(up_w,   wu,  (size_t)I_DIM * H_DIM);
    cvt_w(down_w, wd,  (size_t)H_DIM * I_DIM);

    const float scale = 0.08838834764831845f;  // 1/sqrt(128)

    // fc fusion
    concat_kernel<<<(S_LEN * H2_DIM) / 256, 256>>>(embeds, hidden, cat);
    run_gemm(cat, wfc, x1, S_LEN, H_DIM, H2_DIM, H2_DIM, H2_DIM, H_DIM,
             1.f, fc_b, nullptr, 0, 0, 1, 0, 1, 0, 1, 0);

    // attention block
    rmsnorm_kernel<<<S_LEN, 256>>>(x1, in_nw, h1);
    run_gemm(h1, wq, qf, S_LEN, QDIM,  H_DIM, H_DIM, H_DIM, QDIM,
             1.f, nullptr, nullptr, 0, 0, 1, 0, 1, 0, 1, F_OUTHALF);
    run_gemm(h1, wk, kf, S_LEN, KVDIM, H_DIM, H_DIM, H_DIM, KVDIM,
             1.f, nullptr, nullptr, 0, 0, 1, 0, 1, 0, 1, F_OUTHALF);
    run_gemm(h1, wv, vf, S_LEN, KVDIM, H_DIM, H_DIM, H_DIM, KVDIM,
             1.f, nullptr, nullptr, 0, 0, 1, 0, 1, 0, 1, F_OUTHALF);

    rope_kernel<<<(S_LEN * NHEADS * 64) / 256, 256>>>(qf, NHEADS);
    rope_kernel<<<(S_LEN * NKV * 64) / 256, 256>>>(kf, NKV);
    transpose_kernel<<<dim3(KVDIM / 32, S_LEN / 32), dim3(32, 8)>>>(vf, vt, S_LEN, KVDIM);

    // scores[h] = scale * Q_h K_h^T (fp32 out, causal block skip)
    run_gemm(qf, kf, sc, S_LEN, S_LEN, HEADD, QDIM, KVDIM, S_LEN,
             scale, nullptr, nullptr, 0,
             (long long)HEADD, 1, (long long)HEADD, 4,
             (long long)S_LEN * S_LEN, NHEADS, F_CSKIP);
    softmax_kernel<<<dim3(S_LEN, NHEADS), 256>>>(sc, pr, amask);
    // out[h] = P_h V_h  -> [S, NH*D] fp16; K limited to diagonal block
    run_gemm(pr, vt, ao, S_LEN, HEADD, S_LEN, S_LEN, S_LEN, QDIM,
             1.f, nullptr, nullptr, 0,
             (long long)S_LEN * S_LEN, 1, (long long)HEADD * S_LEN, 4,
             (long long)HEADD, NHEADS, F_OUTHALF | F_PVLIM);

    // o-proj + residual (fp32 out)
    run_gemm(ao, wo, x2, S_LEN, H_DIM, QDIM, QDIM, QDIM, H_DIM,
             1.f, nullptr, x1, H_DIM, 0, 1, 0, 1, 0, 1, 0);

    // MLP block
    rmsnorm_kernel<<<S_LEN, 256>>>(x2, post_nw, h2);
    run_gemm(h2, wg, gf, S_LEN, I_DIM, H_DIM, H_DIM, H_DIM, I_DIM,
             1.f, nullptr, nullptr, 0, 0, 1, 0, 1, 0, 1, F_OUTHALF);
    // up GEMM, epilogue: silu(gate)*up written in place (fp16)
    run_gemm(h2, wu, gf, S_LEN, I_DIM, H_DIM, H_DIM, H_DIM, I_DIM,
             1.f, nullptr, gf, I_DIM, 0, 1, 0, 1, 0, 1,
             F_SILU | F_RESHALF | F_OUTHALF);
    run_gemm(gf, wd, out, S_LEN, H_DIM, I_DIM, I_DIM, I_DIM, H_DIM,
             1.f, nullptr, x2, H_DIM, 0, 1, 0, 1, 0, 1, 0);
}